// round 11
// baseline (speedup 1.0000x reference)
#include <cuda_runtime.h>
#include <cuda_bf16.h>
#include <cuda_fp16.h>
#include <cstdint>

// ============================================================================
// InteractionPruning: out[b,i,j] = f_i^T Z_ij f_j,  Z = clip(sig(M)*1.2-0.1,0,1)
// Split: Z = 0.5 + R,  R = clip(0.6*tanh(M/2), -0.5, 0.5)
//   out = 0.5*S_i*S_j (fp32 exact)  +  f_i^T R f_j  (e4m3 mma.sync m16n8k32)
// v10: FIXED ksg-pair-interleaved B layout (correct LDS.128), main restructured
//      to 256 thr / 8 warps / 1 mtile per warp (half the per-warp registers ->
//      16+ warps/SM), zero-C first MMA, fp16 acc-layout epilogue.
// ============================================================================

#define B_SZ   1024
#define F_SZ   32
#define D_SZ   128
#define NPAIR  496
#define NBT    8

#define R_SCALE     131072.0f      // 2^17
#define R_INVSCALE  (1.0f/131072.0f)

// g_FA8: fp8 A-frag images of feature: [bt][f] x (mt8 x ksg4 x lane32) uint4 = 16KB/tile
// g_RB4: fp8 B-frag images of R:       [p]    x (nt16 x kp2  x lane32) uint4 = 16KB/pair
//        uint4 = {b0,b1}(ksg=2kp) ++ {b0,b1}(ksg=2kp+1)  -- LDS.128-ready
// g_FE : fp16 epilogue images of Fi in ACC layout: [bt][f] x (mt8 x np8 x lane32) uint4
__device__ uint4 g_FA8[NBT * F_SZ * 1024];   // 4 MB
__device__ uint4 g_RB4[NPAIR * 1024];        // 7.9 MB
__device__ uint4 g_FE[NBT * F_SZ * 2048];    // 8 MB
__device__ float g_S[B_SZ * F_SZ];           // row sums of feature

// ---------------------------------------------------------------------------
__device__ __forceinline__ void decode_pair(int p, int& i, int& j) {
    int jj = (int)((1.0f + sqrtf(1.0f + 8.0f * (float)p)) * 0.5f);
    while (jj * (jj - 1) / 2 > p) --jj;
    while ((jj + 1) * jj / 2 <= p) ++jj;
    j = jj;
    i = p - jj * (jj - 1) / 2;
}

__device__ __forceinline__ float gate_r(float m) {
    float x = 0.5f * m;
    if (fabsf(m) < 0.04f) {
        return 0.6f * (x - 0.33333334f * x * x * x);   // rel err < 1e-7
    }
    float s = 1.0f / (1.0f + __expf(-m));
    return fminf(fmaxf(1.2f * s - 0.6f, -0.5f), 0.5f);
}

__device__ __forceinline__ uint32_t pack_e4m3x4(float f0, float f1, float f2, float f3) {
    unsigned short lo, hi;
    asm("cvt.rn.satfinite.e4m3x2.f32 %0, %1, %2;" : "=h"(lo) : "f"(f1), "f"(f0));
    asm("cvt.rn.satfinite.e4m3x2.f32 %0, %1, %2;" : "=h"(hi) : "f"(f3), "f"(f2));
    return (uint32_t)lo | ((uint32_t)hi << 16);
}

__device__ __forceinline__ uint32_t e4m3pair_to_h2(uint32_t dw, int sel) {
    unsigned short hsel = (unsigned short)(sel ? (dw >> 16) : dw);
    uint32_t h2;
    asm("cvt.rn.f16x2.e4m3x2 %0, %1;" : "=r"(h2) : "h"(hsel));
    return h2;
}

__device__ __forceinline__ float2 h2_to_f2(uint32_t u) {
    __half2 h = *reinterpret_cast<__half2*>(&u);
    return __half22float2(h);
}

// mma.sync m16n8k32 row.col f32 += e4m3*e4m3
__device__ __forceinline__ void mma16832(float* c, const uint32_t* a, const uint32_t* b) {
    asm volatile(
        "mma.sync.aligned.m16n8k32.row.col.f32.e4m3.e4m3.f32 "
        "{%0,%1,%2,%3}, {%4,%5,%6,%7}, {%8,%9}, {%0,%1,%2,%3};"
        : "+f"(c[0]), "+f"(c[1]), "+f"(c[2]), "+f"(c[3])
        : "r"(a[0]), "r"(a[1]), "r"(a[2]), "r"(a[3]), "r"(b[0]), "r"(b[1]));
}

// zero-C variant: acc = A*B
__device__ __forceinline__ void mma16832_zc(float* c, const uint32_t* a, const uint32_t* b) {
    asm volatile(
        "mma.sync.aligned.m16n8k32.row.col.f32.e4m3.e4m3.f32 "
        "{%0,%1,%2,%3}, {%4,%5,%6,%7}, {%8,%9}, {%10,%11,%12,%13};"
        : "=f"(c[0]), "=f"(c[1]), "=f"(c[2]), "=f"(c[3])
        : "r"(a[0]), "r"(a[1]), "r"(a[2]), "r"(a[3]), "r"(b[0]), "r"(b[1]),
          "f"(0.f), "f"(0.f), "f"(0.f), "f"(0.f));
}

#define CP_ASYNC16(dst_u32, src_ptr) \
    asm volatile("cp.async.cg.shared.global [%0], [%1], 16;" \
                 :: "r"(dst_u32), "l"(src_ptr) : "memory")
#define CP_COMMIT() asm volatile("cp.async.commit_group;" ::: "memory")
#define CP_WAIT_GROUP(n) asm volatile("cp.async.wait_group %0;" :: "n"(n) : "memory")

// ---------------------------------------------------------------------------
// prep_all: 1504 blocks x 256 threads.
//   blocks [0,512):    feature half-tiles -> fp8 A-frags + fp16 epi-frags + S + zero
//   blocks [512,1504): R half-tiles -> fp8 B-frags, ksg-pair-interleaved uint4
// ---------------------------------------------------------------------------
__global__ void __launch_bounds__(256) prep_all(const float* __restrict__ feature,
                                                const float* __restrict__ matrix,
                                                float4* __restrict__ out4) {
    __shared__ uint32_t stage[64 * 36];
    __shared__ float ssum[64];

    int tid = threadIdx.x, bid = blockIdx.x;
    int lane = tid & 31, w = tid >> 5;

    if (bid < 512) {
        // ---------------- feature half-tile ----------------
        int h = bid & 1, f = (bid >> 1) & 31, bt = bid >> 6;
        const float4* src = reinterpret_cast<const float4*>(
            feature + ((size_t)(bt * 128 + h * 64) * F_SZ + f) * D_SZ);
#pragma unroll
        for (int it = 0; it < 8; it++) {
            int rl = it * 8 + w;
            float4 v = src[(size_t)rl * 1024 + lane];
            stage[rl * 36 + lane] = pack_e4m3x4(v.x, v.y, v.z, v.w);
            float s = v.x + v.y + v.z + v.w;
#pragma unroll
            for (int o = 16; o; o >>= 1) s += __shfl_xor_sync(0xffffffffu, s, o);
            if (lane == 0) ssum[rl] = s;
        }
        __syncthreads();

        if (tid < 64) g_S[(bt * 128 + h * 64 + tid) * F_SZ + f] = ssum[tid];

#pragma unroll
        for (int z = 0; z < 2; z++)
            out4[(size_t)bid * 512 + z * 256 + tid] = make_float4(0.f, 0.f, 0.f, 0.f);

        // A-frag gathers: 16 warp-tasks (mtl4 x ksg4), each warp does 2
        uint4* dstA = g_FA8 + (size_t)(bt * F_SZ + f) * 1024;
#pragma unroll
        for (int t = 0; t < 2; t++) {
            int task = w + t * 8;
            int mtl = task >> 2, ksg = task & 3;
            int b0 = mtl * 16 + (lane >> 2), b1 = b0 + 8;
            int c = ksg * 8 + (lane & 3);
            uint4 o;
            o.x = stage[b0 * 36 + c];
            o.y = stage[b1 * 36 + c];
            o.z = stage[b0 * 36 + c + 4];
            o.w = stage[b1 * 36 + c + 4];
            int mt = h * 4 + mtl;
            dstA[(mt * 4 + ksg) * 32 + lane] = o;
        }

        // fp16 epilogue frags in ACC layout
        uint4* dstE = g_FE + (size_t)(bt * F_SZ + f) * 2048;
        int sel = lane & 1;
        int dq = (lane & 3) >> 1;
#pragma unroll
        for (int t = 0; t < 4; t++) {
            int g2 = t * 8 + w;
            int mtl = g2 >> 3, np = g2 & 7;
            int r0 = mtl * 16 + (lane >> 2), r1 = r0 + 8;
            int dwc = 4 * np + dq;
            uint32_t dw0a = stage[r0 * 36 + dwc];
            uint32_t dw1a = stage[r1 * 36 + dwc];
            uint32_t dw0b = stage[r0 * 36 + dwc + 2];
            uint32_t dw1b = stage[r1 * 36 + dwc + 2];
            uint4 o;
            o.x = e4m3pair_to_h2(dw0a, sel);
            o.y = e4m3pair_to_h2(dw1a, sel);
            o.z = e4m3pair_to_h2(dw0b, sel);
            o.w = e4m3pair_to_h2(dw1b, sel);
            int mt = h * 4 + mtl;
            dstE[(mt * 8 + np) * 32 + lane] = o;
        }
    } else {
        // ---------------- R half-tile ----------------
        int idx = bid - 512;
        int h = idx & 1, p = idx >> 1;
        int i, j; decode_pair(p, i, j);
        const float4* src = reinterpret_cast<const float4*>(
            matrix + (((size_t)(i * F_SZ + j) * D_SZ) + h * 64) * D_SZ);
#pragma unroll
        for (int it = 0; it < 8; it++) {
            int rl = it * 8 + w;
            float4 v = src[(size_t)rl * 32 + lane];
            stage[rl * 36 + lane] = pack_e4m3x4(gate_r(v.x) * R_SCALE,
                                                gate_r(v.y) * R_SCALE,
                                                gate_r(v.z) * R_SCALE,
                                                gate_r(v.w) * R_SCALE);
        }
        __syncthreads();

        // B-frag gathers, ksg-pair interleaved: 16 warp-tasks (ntl8 x kp2)
        // uint4 = {stage[c0], stage[c0+4], stage[c0+8], stage[c0+12]}
        //       = b0,b1 of ksg=2kp  ++  b0,b1 of ksg=2kp+1   (same lane)
        uint4* dst = g_RB4 + (size_t)p * 1024;
#pragma unroll
        for (int t = 0; t < 2; t++) {
            int task = w + t * 8;
            int ntl = task >> 1, kp = task & 1;
            int dl = ntl * 8 + (lane >> 2);
            int c0 = kp * 16 + (lane & 3);
            uint4 o;
            o.x = stage[dl * 36 + c0];
            o.y = stage[dl * 36 + c0 + 4];
            o.z = stage[dl * 36 + c0 + 8];
            o.w = stage[dl * 36 + c0 + 12];
            int nt = h * 8 + ntl;
            dst[(nt * 2 + kp) * 32 + lane] = o;
        }
    }
}

// ---------------------------------------------------------------------------
// Main kernel: CTA = (pair p, batch tile bt). 256 threads, 8 warps,
// one 16-row mtile per warp (halved per-warp registers -> more warps/SM).
// SMEM: sA (16KB) | sB (16KB) = 32KB.
// ---------------------------------------------------------------------------
__global__ void __launch_bounds__(256) main_mma(float* __restrict__ out) {
    extern __shared__ char sm[];
    int tid = threadIdx.x, w = tid >> 5, lane = tid & 31;
    int p = blockIdx.x >> 3, bt = blockIdx.x & 7;
    int i, j; decode_pair(p, i, j);

    uint32_t sb = 0;
    asm("{ .reg .u64 t; cvta.to.shared.u64 t, %1; cvt.u32.u64 %0, t; }"
        : "=r"(sb) : "l"(sm));

    const uint4* gA = g_FA8 + (size_t)(bt * F_SZ + j) * 1024;
    const uint4* gB = g_RB4 + (size_t)p * 1024;
    const uint4* gE = g_FE + (size_t)(bt * F_SZ + i) * 2048;

#pragma unroll
    for (int k = 0; k < 4; k++)
        CP_ASYNC16(sb + (uint32_t)(tid + 256 * k) * 16, (const void*)(gA + tid + 256 * k));
    CP_COMMIT();
#pragma unroll
    for (int k = 0; k < 4; k++)
        CP_ASYNC16(sb + 16384u + (uint32_t)(tid + 256 * k) * 16, (const void*)(gB + tid + 256 * k));
    CP_COMMIT();

    const uint4* sA  = reinterpret_cast<const uint4*>(sm);           // [mt8][ksg4][lane32]
    const uint4* sB4 = reinterpret_cast<const uint4*>(sm + 16384);   // [nt16][kp2][lane32]

    CP_WAIT_GROUP(1);
    __syncthreads();

    // A fragments for this warp's 16 rows (mtile w)
    uint32_t Afr[4][4];
#pragma unroll
    for (int ksg = 0; ksg < 4; ksg++) {
        uint4 v = sA[(w * 4 + ksg) * 32 + lane];
        Afr[ksg][0] = v.x; Afr[ksg][1] = v.y;
        Afr[ksg][2] = v.z; Afr[ksg][3] = v.w;
    }

    CP_WAIT_GROUP(0);
    __syncthreads();

    float pacc[2] = {0.f, 0.f};

#pragma unroll
    for (int g4 = 0; g4 < 4; g4++) {                // n (=d) in 4 groups of 32
        // epilogue Fi frags (fp16 acc layout): np = 2g4+s covers ntl=2s, 2s+1
        uint4 ep[2];
#pragma unroll
        for (int s = 0; s < 2; s++)
            ep[s] = gE[(w * 8 + (g4 * 2 + s)) * 32 + lane];

        float acc[4][4];

#pragma unroll
        for (int kp = 0; kp < 2; kp++) {            // ksg pairs: (0,1), (2,3)
            uint32_t Bfr[4][4];
#pragma unroll
            for (int nt = 0; nt < 4; nt++) {
                uint4 v = sB4[((g4 * 4 + nt) * 2 + kp) * 32 + lane];
                Bfr[nt][0] = v.x; Bfr[nt][1] = v.y;   // ksg = 2kp
                Bfr[nt][2] = v.z; Bfr[nt][3] = v.w;   // ksg = 2kp+1
            }
#pragma unroll
            for (int kh = 0; kh < 2; kh++) {
                int ksg = kp * 2 + kh;
#pragma unroll
                for (int nt = 0; nt < 4; nt++) {
                    if (ksg == 0)
                        mma16832_zc(acc[nt], Afr[0], &Bfr[nt][0]);
                    else
                        mma16832(acc[nt], Afr[ksg], &Bfr[nt][kh * 2]);
                }
            }
        }

        // epilogue: ntl = 2s+h; h=0 -> (x,y), h=1 -> (z,w)
#pragma unroll
        for (int s = 0; s < 2; s++) {
#pragma unroll
            for (int h = 0; h < 2; h++) {
                int ntl = 2 * s + h;
                uint32_t lo = h ? ep[s].z : ep[s].x;
                uint32_t hi = h ? ep[s].w : ep[s].y;
                float2 f0 = h2_to_f2(lo);
                float2 f1 = h2_to_f2(hi);
                pacc[0] += acc[ntl][0] * f0.x + acc[ntl][1] * f0.y;
                pacc[1] += acc[ntl][2] * f1.x + acc[ntl][3] * f1.y;
            }
        }
    }

    // quad reduce (cols live on lanes sharing lane>>2)
#pragma unroll
    for (int hh = 0; hh < 2; hh++) {
        pacc[hh] += __shfl_xor_sync(0xffffffffu, pacc[hh], 1);
        pacc[hh] += __shfl_xor_sync(0xffffffffu, pacc[hh], 2);
    }

    if ((lane & 3) == 0) {
#pragma unroll
        for (int hh = 0; hh < 2; hh++) {
            int row = w * 16 + (lane >> 2) + hh * 8;
            int bg = bt * 128 + row;
            float res = 0.5f * g_S[bg * F_SZ + i] * g_S[bg * F_SZ + j]
                      + pacc[hh] * R_INVSCALE;
            out[(size_t)bg * (F_SZ * F_SZ) + i * F_SZ + j] = res;
        }
    }
}

// ---------------------------------------------------------------------------
extern "C" void kernel_launch(void* const* d_in, const int* in_sizes, int n_in,
                              void* d_out, int out_size) {
    const float* feature = (const float*)d_in[0];   // [1024, 32, 128] f32
    const float* matrix  = (const float*)d_in[1];   // [32, 32, 128, 128] f32
    float* out = (float*)d_out;                     // [1024, 32, 32] f32

    cudaFuncSetAttribute(main_mma, cudaFuncAttributeMaxDynamicSharedMemorySize, 32768);

    prep_all<<<512 + 2 * NPAIR, 256>>>(feature, matrix, (float4*)out);  // 1504 blocks
    main_mma<<<NPAIR * NBT, 256, 32768>>>(out);                         // 3968 blocks
}

// round 13
// speedup vs baseline: 1.1536x; 1.1536x over previous
#include <cuda_runtime.h>
#include <cuda_bf16.h>
#include <cuda_fp16.h>
#include <cstdint>

// ============================================================================
// InteractionPruning: out[b,i,j] = f_i^T Z_ij f_j,  Z = clip(sig(M)*1.2-0.1,0,1)
// Split: Z = 0.5 + R,  R = clip(0.6*tanh(M/2), -0.5, 0.5)
//   out = 0.5*S_i*S_j (fp32 exact)  +  f_i^T R f_j  (e4m3 mma.sync m16n8k32)
// v12 = v7 config (128 thr, mt=2/warp, fp8 epilogue, 3 CTAs/SM) +
//       LDS.128 interleaved B loads (correct g_RB4 layout, validated R11) +
//       zero-C first MMA. Prep drops g_FE (unused).
// ============================================================================

#define B_SZ   1024
#define F_SZ   32
#define D_SZ   128
#define NPAIR  496
#define NBT    8

#define R_SCALE     131072.0f      // 2^17
#define R_INVSCALE  (1.0f/131072.0f)

// g_FA8: fp8 A-frag images of feature: [bt][f] x (mt8 x ksg4 x lane32) uint4 = 16KB/tile
// g_RB4: fp8 B-frag images of R:       [p]    x (nt16 x kp2  x lane32) uint4 = 16KB/pair
//        uint4 = {b0,b1}(ksg=2kp) ++ {b0,b1}(ksg=2kp+1)  (same lane) -- LDS.128-ready
__device__ uint4 g_FA8[NBT * F_SZ * 1024];   // 4 MB
__device__ uint4 g_RB4[NPAIR * 1024];        // 7.9 MB
__device__ float g_S[B_SZ * F_SZ];           // row sums of feature

// ---------------------------------------------------------------------------
__device__ __forceinline__ void decode_pair(int p, int& i, int& j) {
    int jj = (int)((1.0f + sqrtf(1.0f + 8.0f * (float)p)) * 0.5f);
    while (jj * (jj - 1) / 2 > p) --jj;
    while ((jj + 1) * jj / 2 <= p) ++jj;
    j = jj;
    i = p - jj * (jj - 1) / 2;
}

__device__ __forceinline__ float gate_r(float m) {
    float x = 0.5f * m;
    if (fabsf(m) < 0.04f) {
        return 0.6f * (x - 0.33333334f * x * x * x);   // rel err < 1e-7
    }
    float s = 1.0f / (1.0f + __expf(-m));
    return fminf(fmaxf(1.2f * s - 0.6f, -0.5f), 0.5f);
}

__device__ __forceinline__ uint32_t pack_e4m3x4(float f0, float f1, float f2, float f3) {
    unsigned short lo, hi;
    asm("cvt.rn.satfinite.e4m3x2.f32 %0, %1, %2;" : "=h"(lo) : "f"(f1), "f"(f0));
    asm("cvt.rn.satfinite.e4m3x2.f32 %0, %1, %2;" : "=h"(hi) : "f"(f3), "f"(f2));
    return (uint32_t)lo | ((uint32_t)hi << 16);
}

// select fp8 pair (sel=0: bytes 0-1, sel=1: bytes 2-3) -> float2
__device__ __forceinline__ float2 fp8pair_to_f2(uint32_t dw, int sel) {
    unsigned short h = (unsigned short)(sel ? (dw >> 16) : dw);
    uint32_t h2;
    asm("cvt.rn.f16x2.e4m3x2 %0, %1;" : "=r"(h2) : "h"(h));
    __half2 hh = *reinterpret_cast<__half2*>(&h2);
    return __half22float2(hh);
}

// mma.sync m16n8k32 row.col f32 += e4m3*e4m3
__device__ __forceinline__ void mma16832(float* c, const uint32_t* a, const uint32_t* b) {
    asm volatile(
        "mma.sync.aligned.m16n8k32.row.col.f32.e4m3.e4m3.f32 "
        "{%0,%1,%2,%3}, {%4,%5,%6,%7}, {%8,%9}, {%0,%1,%2,%3};"
        : "+f"(c[0]), "+f"(c[1]), "+f"(c[2]), "+f"(c[3])
        : "r"(a[0]), "r"(a[1]), "r"(a[2]), "r"(a[3]), "r"(b[0]), "r"(b[1]));
}

// zero-C variant: acc = A*B (C = RZ) — no explicit acc zeroing
__device__ __forceinline__ void mma16832_zc(float* c, const uint32_t* a, const uint32_t* b) {
    asm volatile(
        "mma.sync.aligned.m16n8k32.row.col.f32.e4m3.e4m3.f32 "
        "{%0,%1,%2,%3}, {%4,%5,%6,%7}, {%8,%9}, {%10,%11,%12,%13};"
        : "=f"(c[0]), "=f"(c[1]), "=f"(c[2]), "=f"(c[3])
        : "r"(a[0]), "r"(a[1]), "r"(a[2]), "r"(a[3]), "r"(b[0]), "r"(b[1]),
          "f"(0.f), "f"(0.f), "f"(0.f), "f"(0.f));
}

#define CP_ASYNC16(dst_u32, src_ptr) \
    asm volatile("cp.async.cg.shared.global [%0], [%1], 16;" \
                 :: "r"(dst_u32), "l"(src_ptr) : "memory")
#define CP_COMMIT() asm volatile("cp.async.commit_group;" ::: "memory")
#define CP_WAIT_GROUP(n) asm volatile("cp.async.wait_group %0;" :: "n"(n) : "memory")

// ---------------------------------------------------------------------------
// prep_all: 1504 blocks x 256 threads.
//   blocks [0,512):    feature half-tiles -> fp8 A-frags + row sums S + zero out
//   blocks [512,1504): R half-tiles -> fp8 B-frags, ksg-pair-interleaved uint4
// ---------------------------------------------------------------------------
__global__ void __launch_bounds__(256) prep_all(const float* __restrict__ feature,
                                                const float* __restrict__ matrix,
                                                float4* __restrict__ out4) {
    __shared__ uint32_t stage[64 * 36];
    __shared__ float ssum[64];

    int tid = threadIdx.x, bid = blockIdx.x;
    int lane = tid & 31, w = tid >> 5;

    if (bid < 512) {
        // ---------------- feature half-tile ----------------
        int h = bid & 1, f = (bid >> 1) & 31, bt = bid >> 6;
        const float4* src = reinterpret_cast<const float4*>(
            feature + ((size_t)(bt * 128 + h * 64) * F_SZ + f) * D_SZ);
#pragma unroll
        for (int it = 0; it < 8; it++) {
            int rl = it * 8 + w;
            float4 v = src[(size_t)rl * 1024 + lane];
            stage[rl * 36 + lane] = pack_e4m3x4(v.x, v.y, v.z, v.w);
            float s = v.x + v.y + v.z + v.w;
#pragma unroll
            for (int o = 16; o; o >>= 1) s += __shfl_xor_sync(0xffffffffu, s, o);
            if (lane == 0) ssum[rl] = s;
        }
        __syncthreads();

        if (tid < 64) g_S[(bt * 128 + h * 64 + tid) * F_SZ + f] = ssum[tid];

#pragma unroll
        for (int z = 0; z < 2; z++)
            out4[(size_t)bid * 512 + z * 256 + tid] = make_float4(0.f, 0.f, 0.f, 0.f);

        // A-frag gathers: 16 warp-tasks (mtl4 x ksg4), each warp does 2
        uint4* dstA = g_FA8 + (size_t)(bt * F_SZ + f) * 1024;
#pragma unroll
        for (int t = 0; t < 2; t++) {
            int task = w + t * 8;
            int mtl = task >> 2, ksg = task & 3;
            int b0 = mtl * 16 + (lane >> 2), b1 = b0 + 8;
            int c = ksg * 8 + (lane & 3);
            uint4 o;
            o.x = stage[b0 * 36 + c];
            o.y = stage[b1 * 36 + c];
            o.z = stage[b0 * 36 + c + 4];
            o.w = stage[b1 * 36 + c + 4];
            int mt = h * 4 + mtl;
            dstA[(mt * 4 + ksg) * 32 + lane] = o;
        }
    } else {
        // ---------------- R half-tile ----------------
        int idx = bid - 512;
        int h = idx & 1, p = idx >> 1;
        int i, j; decode_pair(p, i, j);
        const float4* src = reinterpret_cast<const float4*>(
            matrix + (((size_t)(i * F_SZ + j) * D_SZ) + h * 64) * D_SZ);
#pragma unroll
        for (int it = 0; it < 8; it++) {
            int rl = it * 8 + w;
            float4 v = src[(size_t)rl * 32 + lane];
            stage[rl * 36 + lane] = pack_e4m3x4(gate_r(v.x) * R_SCALE,
                                                gate_r(v.y) * R_SCALE,
                                                gate_r(v.z) * R_SCALE,
                                                gate_r(v.w) * R_SCALE);
        }
        __syncthreads();

        // B-frag gathers, ksg-pair interleaved (validated in R11):
        // uint4 = {stage[c0], stage[c0+4], stage[c0+8], stage[c0+12]}
        //       = b0,b1 of ksg=2kp  ++  b0,b1 of ksg=2kp+1   (same lane)
        uint4* dst = g_RB4 + (size_t)p * 1024;
#pragma unroll
        for (int t = 0; t < 2; t++) {
            int task = w + t * 8;
            int ntl = task >> 1, kp = task & 1;
            int dl = ntl * 8 + (lane >> 2);
            int c0 = kp * 16 + (lane & 3);
            uint4 o;
            o.x = stage[dl * 36 + c0];
            o.y = stage[dl * 36 + c0 + 4];
            o.z = stage[dl * 36 + c0 + 8];
            o.w = stage[dl * 36 + c0 + 12];
            int nt = h * 8 + ntl;
            dst[(nt * 2 + kp) * 32 + lane] = o;
        }
    }
}

// ---------------------------------------------------------------------------
// Main kernel: CTA = (pair p, batch tile bt). 4 warps, 2 mtiles (32 rows) each.
// SMEM: sA (16KB) | sB (16KB) = 32KB, 3 CTAs/SM.
// Fi epilogue pairs extracted from the fp8 A-image of tile i via LDG + cvt.
// ---------------------------------------------------------------------------
__global__ void __launch_bounds__(128, 3) main_mma(float* __restrict__ out) {
    extern __shared__ char sm[];
    int tid = threadIdx.x, w = tid >> 5, lane = tid & 31;
    int p = blockIdx.x >> 3, bt = blockIdx.x & 7;
    int i, j; decode_pair(p, i, j);

    uint32_t sb = 0;
    asm("{ .reg .u64 t; cvta.to.shared.u64 t, %1; cvt.u32.u64 %0, t; }"
        : "=r"(sb) : "l"(sm));

    const uint4* gA = g_FA8 + (size_t)(bt * F_SZ + j) * 1024;
    const uint4* gB = g_RB4 + (size_t)p * 1024;
    const uint4* gC = g_FA8 + (size_t)(bt * F_SZ + i) * 1024;

#pragma unroll
    for (int k = 0; k < 8; k++)
        CP_ASYNC16(sb + (uint32_t)(tid + 128 * k) * 16, (const void*)(gA + tid + 128 * k));
    CP_COMMIT();
#pragma unroll
    for (int k = 0; k < 8; k++)
        CP_ASYNC16(sb + 16384u + (uint32_t)(tid + 128 * k) * 16, (const void*)(gB + tid + 128 * k));
    CP_COMMIT();

    const uint4* sA  = reinterpret_cast<const uint4*>(sm);           // [mt8][ksg4][lane32]
    const uint4* sB4 = reinterpret_cast<const uint4*>(sm + 16384);   // [nt16][kp2][lane32]

    CP_WAIT_GROUP(1);
    __syncthreads();

    // A fragments for this warp's 32 rows (mtiles 2w, 2w+1)
    uint32_t Afr[2][4][4];
#pragma unroll
    for (int mt = 0; mt < 2; mt++) {
#pragma unroll
        for (int ksg = 0; ksg < 4; ksg++) {
            uint4 v = sA[((2 * w + mt) * 4 + ksg) * 32 + lane];
            Afr[mt][ksg][0] = v.x; Afr[mt][ksg][1] = v.y;
            Afr[mt][ksg][2] = v.z; Afr[mt][ksg][3] = v.w;
        }
    }

    CP_WAIT_GROUP(0);
    __syncthreads();

    int sel = lane & 1;                // fp8 pair within dword
    int lq  = ((lane & 3) >> 1);       // dword sub-select
    float pacc[2][2] = {{0.f, 0.f}, {0.f, 0.f}};

#pragma unroll
    for (int g4 = 0; g4 < 4; g4++) {                // n (=d) in 4 groups of 32
        // epilogue Fi dwords: fp8 A-frag image (mt''=2w+mt, ksg'=g4), remapped lane
        uint4 ep[2][2];
#pragma unroll
        for (int mt = 0; mt < 2; mt++) {
#pragma unroll
            for (int s = 0; s < 2; s++) {
                int lp = (lane >> 2) * 4 + s * 2 + lq;
                ep[mt][s] = gC[((2 * w + mt) * 4 + g4) * 32 + lp];
            }
        }

        float acc[2][4][4];

#pragma unroll
        for (int kp = 0; kp < 2; kp++) {            // ksg pairs: (0,1), (2,3)
            // one LDS.128 per nt feeds two k-steps (same-lane interleave)
            uint32_t Bfr[4][4];
#pragma unroll
            for (int nt = 0; nt < 4; nt++) {
                uint4 v = sB4[((g4 * 4 + nt) * 2 + kp) * 32 + lane];
                Bfr[nt][0] = v.x; Bfr[nt][1] = v.y;   // ksg = 2kp
                Bfr[nt][2] = v.z; Bfr[nt][3] = v.w;   // ksg = 2kp+1
            }
#pragma unroll
            for (int kh = 0; kh < 2; kh++) {
                int ksg = kp * 2 + kh;
#pragma unroll
                for (int mt = 0; mt < 2; mt++) {
#pragma unroll
                    for (int nt = 0; nt < 4; nt++) {
                        if (ksg == 0)
                            mma16832_zc(acc[mt][nt], Afr[mt][0], &Bfr[nt][0]);
                        else
                            mma16832(acc[mt][nt], Afr[mt][ksg], &Bfr[nt][kh * 2]);
                    }
                }
            }
        }

        // epilogue (v7 mapping): nt0 -> ep[mt][0].x/.y ; nt1 -> ep[mt][1].x/.y
        //                        nt2 -> ep[mt][0].z/.w ; nt3 -> ep[mt][1].z/.w
#pragma unroll
        for (int mt = 0; mt < 2; mt++) {
#pragma unroll
            for (int nt = 0; nt < 4; nt++) {
                const uint4& e = ep[mt][nt & 1];
                uint32_t dw0 = (nt < 2) ? e.x : e.z;
                uint32_t dw1 = (nt < 2) ? e.y : e.w;
                float2 f0 = fp8pair_to_f2(dw0, sel);
                float2 f1 = fp8pair_to_f2(dw1, sel);
                pacc[mt][0] += acc[mt][nt][0] * f0.x + acc[mt][nt][1] * f0.y;
                pacc[mt][1] += acc[mt][nt][2] * f1.x + acc[mt][nt][3] * f1.y;
            }
        }
    }

    // quad reduce (cols live on lanes sharing lane>>2)
#pragma unroll
    for (int mt = 0; mt < 2; mt++)
#pragma unroll
        for (int hh = 0; hh < 2; hh++) {
            pacc[mt][hh] += __shfl_xor_sync(0xffffffffu, pacc[mt][hh], 1);
            pacc[mt][hh] += __shfl_xor_sync(0xffffffffu, pacc[mt][hh], 2);
        }

    if ((lane & 3) == 0) {
#pragma unroll
        for (int mt = 0; mt < 2; mt++) {
#pragma unroll
            for (int hh = 0; hh < 2; hh++) {
                int row = (2 * w + mt) * 16 + (lane >> 2) + hh * 8;
                int bg = bt * 128 + row;
                float res = 0.5f * g_S[bg * F_SZ + i] * g_S[bg * F_SZ + j]
                          + pacc[mt][hh] * R_INVSCALE;
                out[(size_t)bg * (F_SZ * F_SZ) + i * F_SZ + j] = res;
            }
        }
    }
}

// ---------------------------------------------------------------------------
extern "C" void kernel_launch(void* const* d_in, const int* in_sizes, int n_in,
                              void* d_out, int out_size) {
    const float* feature = (const float*)d_in[0];   // [1024, 32, 128] f32
    const float* matrix  = (const float*)d_in[1];   // [32, 32, 128, 128] f32
    float* out = (float*)d_out;                     // [1024, 32, 32] f32

    cudaFuncSetAttribute(main_mma, cudaFuncAttributeMaxDynamicSharedMemorySize, 32768);

    prep_all<<<512 + 2 * NPAIR, 256>>>(feature, matrix, (float4*)out);  // 1504 blocks
    main_mma<<<NPAIR * NBT, 128, 32768>>>(out);                         // 3968 blocks
}

// round 15
// speedup vs baseline: 1.1580x; 1.0038x over previous
#include <cuda_runtime.h>
#include <cuda_bf16.h>
#include <cuda_fp16.h>
#include <cstdint>

// ============================================================================
// InteractionPruning: out[b,i,j] = f_i^T Z_ij f_j,  Z = clip(sig(M)*1.2-0.1,0,1)
// Split: Z = 0.5 + R,  R = clip(0.6*tanh(M/2), -0.5, 0.5)
//   out = 0.5*S_i*S_j (fp32 exact)  +  f_i^T R f_j  (e4m3 mma.sync m16n8k32)
// v12 = v7 config (128 thr, mt=2/warp, fp8 epilogue, 3 CTAs/SM) +
//       LDS.128 interleaved B loads (correct g_RB4 layout, validated R11) +
//       zero-C first MMA. Prep drops g_FE (unused).
// ============================================================================

#define B_SZ   1024
#define F_SZ   32
#define D_SZ   128
#define NPAIR  496
#define NBT    8

#define R_SCALE     131072.0f      // 2^17
#define R_INVSCALE  (1.0f/131072.0f)

// g_FA8: fp8 A-frag images of feature: [bt][f] x (mt8 x ksg4 x lane32) uint4 = 16KB/tile
// g_RB4: fp8 B-frag images of R:       [p]    x (nt16 x kp2  x lane32) uint4 = 16KB/pair
//        uint4 = {b0,b1}(ksg=2kp) ++ {b0,b1}(ksg=2kp+1)  (same lane) -- LDS.128-ready
__device__ uint4 g_FA8[NBT * F_SZ * 1024];   // 4 MB
__device__ uint4 g_RB4[NPAIR * 1024];        // 7.9 MB
__device__ float g_S[B_SZ * F_SZ];           // row sums of feature

// ---------------------------------------------------------------------------
__device__ __forceinline__ void decode_pair(int p, int& i, int& j) {
    int jj = (int)((1.0f + sqrtf(1.0f + 8.0f * (float)p)) * 0.5f);
    while (jj * (jj - 1) / 2 > p) --jj;
    while ((jj + 1) * jj / 2 <= p) ++jj;
    j = jj;
    i = p - jj * (jj - 1) / 2;
}

__device__ __forceinline__ float gate_r(float m) {
    float x = 0.5f * m;
    if (fabsf(m) < 0.04f) {
        return 0.6f * (x - 0.33333334f * x * x * x);   // rel err < 1e-7
    }
    float s = 1.0f / (1.0f + __expf(-m));
    return fminf(fmaxf(1.2f * s - 0.6f, -0.5f), 0.5f);
}

__device__ __forceinline__ uint32_t pack_e4m3x4(float f0, float f1, float f2, float f3) {
    unsigned short lo, hi;
    asm("cvt.rn.satfinite.e4m3x2.f32 %0, %1, %2;" : "=h"(lo) : "f"(f1), "f"(f0));
    asm("cvt.rn.satfinite.e4m3x2.f32 %0, %1, %2;" : "=h"(hi) : "f"(f3), "f"(f2));
    return (uint32_t)lo | ((uint32_t)hi << 16);
}

// select fp8 pair (sel=0: bytes 0-1, sel=1: bytes 2-3) -> float2
__device__ __forceinline__ float2 fp8pair_to_f2(uint32_t dw, int sel) {
    unsigned short h = (unsigned short)(sel ? (dw >> 16) : dw);
    uint32_t h2;
    asm("cvt.rn.f16x2.e4m3x2 %0, %1;" : "=r"(h2) : "h"(h));
    __half2 hh = *reinterpret_cast<__half2*>(&h2);
    return __half22float2(hh);
}

// mma.sync m16n8k32 row.col f32 += e4m3*e4m3
__device__ __forceinline__ void mma16832(float* c, const uint32_t* a, const uint32_t* b) {
    asm volatile(
        "mma.sync.aligned.m16n8k32.row.col.f32.e4m3.e4m3.f32 "
        "{%0,%1,%2,%3}, {%4,%5,%6,%7}, {%8,%9}, {%0,%1,%2,%3};"
        : "+f"(c[0]), "+f"(c[1]), "+f"(c[2]), "+f"(c[3])
        : "r"(a[0]), "r"(a[1]), "r"(a[2]), "r"(a[3]), "r"(b[0]), "r"(b[1]));
}

// zero-C variant: acc = A*B (C = RZ) — no explicit acc zeroing
__device__ __forceinline__ void mma16832_zc(float* c, const uint32_t* a, const uint32_t* b) {
    asm volatile(
        "mma.sync.aligned.m16n8k32.row.col.f32.e4m3.e4m3.f32 "
        "{%0,%1,%2,%3}, {%4,%5,%6,%7}, {%8,%9}, {%10,%11,%12,%13};"
        : "=f"(c[0]), "=f"(c[1]), "=f"(c[2]), "=f"(c[3])
        : "r"(a[0]), "r"(a[1]), "r"(a[2]), "r"(a[3]), "r"(b[0]), "r"(b[1]),
          "f"(0.f), "f"(0.f), "f"(0.f), "f"(0.f));
}

#define CP_ASYNC16(dst_u32, src_ptr) \
    asm volatile("cp.async.cg.shared.global [%0], [%1], 16;" \
                 :: "r"(dst_u32), "l"(src_ptr) : "memory")
#define CP_COMMIT() asm volatile("cp.async.commit_group;" ::: "memory")
#define CP_WAIT_GROUP(n) asm volatile("cp.async.wait_group %0;" :: "n"(n) : "memory")

// ---------------------------------------------------------------------------
// prep_all: 1504 blocks x 256 threads.
//   blocks [0,512):    feature half-tiles -> fp8 A-frags + row sums S + zero out
//   blocks [512,1504): R half-tiles -> fp8 B-frags, ksg-pair-interleaved uint4
// ---------------------------------------------------------------------------
__global__ void __launch_bounds__(256) prep_all(const float* __restrict__ feature,
                                                const float* __restrict__ matrix,
                                                float4* __restrict__ out4) {
    __shared__ uint32_t stage[64 * 36];
    __shared__ float ssum[64];

    int tid = threadIdx.x, bid = blockIdx.x;
    int lane = tid & 31, w = tid >> 5;

    if (bid < 512) {
        // ---------------- feature half-tile ----------------
        int h = bid & 1, f = (bid >> 1) & 31, bt = bid >> 6;
        const float4* src = reinterpret_cast<const float4*>(
            feature + ((size_t)(bt * 128 + h * 64) * F_SZ + f) * D_SZ);
#pragma unroll
        for (int it = 0; it < 8; it++) {
            int rl = it * 8 + w;
            float4 v = src[(size_t)rl * 1024 + lane];
            stage[rl * 36 + lane] = pack_e4m3x4(v.x, v.y, v.z, v.w);
            float s = v.x + v.y + v.z + v.w;
#pragma unroll
            for (int o = 16; o; o >>= 1) s += __shfl_xor_sync(0xffffffffu, s, o);
            if (lane == 0) ssum[rl] = s;
        }
        __syncthreads();

        if (tid < 64) g_S[(bt * 128 + h * 64 + tid) * F_SZ + f] = ssum[tid];

#pragma unroll
        for (int z = 0; z < 2; z++)
            out4[(size_t)bid * 512 + z * 256 + tid] = make_float4(0.f, 0.f, 0.f, 0.f);

        // A-frag gathers: 16 warp-tasks (mtl4 x ksg4), each warp does 2
        uint4* dstA = g_FA8 + (size_t)(bt * F_SZ + f) * 1024;
#pragma unroll
        for (int t = 0; t < 2; t++) {
            int task = w + t * 8;
            int mtl = task >> 2, ksg = task & 3;
            int b0 = mtl * 16 + (lane >> 2), b1 = b0 + 8;
            int c = ksg * 8 + (lane & 3);
            uint4 o;
            o.x = stage[b0 * 36 + c];
            o.y = stage[b1 * 36 + c];
            o.z = stage[b0 * 36 + c + 4];
            o.w = stage[b1 * 36 + c + 4];
            int mt = h * 4 + mtl;
            dstA[(mt * 4 + ksg) * 32 + lane] = o;
        }
    } else {
        // ---------------- R half-tile ----------------
        int idx = bid - 512;
        int h = idx & 1, p = idx >> 1;
        int i, j; decode_pair(p, i, j);
        const float4* src = reinterpret_cast<const float4*>(
            matrix + (((size_t)(i * F_SZ + j) * D_SZ) + h * 64) * D_SZ);
#pragma unroll
        for (int it = 0; it < 8; it++) {
            int rl = it * 8 + w;
            float4 v = src[(size_t)rl * 32 + lane];
            stage[rl * 36 + lane] = pack_e4m3x4(gate_r(v.x) * R_SCALE,
                                                gate_r(v.y) * R_SCALE,
                                                gate_r(v.z) * R_SCALE,
                                                gate_r(v.w) * R_SCALE);
        }
        __syncthreads();

        // B-frag gathers, ksg-pair interleaved (validated in R11):
        // uint4 = {stage[c0], stage[c0+4], stage[c0+8], stage[c0+12]}
        //       = b0,b1 of ksg=2kp  ++  b0,b1 of ksg=2kp+1   (same lane)
        uint4* dst = g_RB4 + (size_t)p * 1024;
#pragma unroll
        for (int t = 0; t < 2; t++) {
            int task = w + t * 8;
            int ntl = task >> 1, kp = task & 1;
            int dl = ntl * 8 + (lane >> 2);
            int c0 = kp * 16 + (lane & 3);
            uint4 o;
            o.x = stage[dl * 36 + c0];
            o.y = stage[dl * 36 + c0 + 4];
            o.z = stage[dl * 36 + c0 + 8];
            o.w = stage[dl * 36 + c0 + 12];
            int nt = h * 8 + ntl;
            dst[(nt * 2 + kp) * 32 + lane] = o;
        }
    }
}

// ---------------------------------------------------------------------------
// Main kernel: CTA = (pair p, batch tile bt). 4 warps, 2 mtiles (32 rows) each.
// SMEM: sA (16KB) | sB (16KB) = 32KB, 3 CTAs/SM.
// Fi epilogue pairs extracted from the fp8 A-image of tile i via LDG + cvt.
// ---------------------------------------------------------------------------
__global__ void __launch_bounds__(128, 3) main_mma(float* __restrict__ out) {
    extern __shared__ char sm[];
    int tid = threadIdx.x, w = tid >> 5, lane = tid & 31;
    int p = blockIdx.x >> 3, bt = blockIdx.x & 7;
    int i, j; decode_pair(p, i, j);

    uint32_t sb = 0;
    asm("{ .reg .u64 t; cvta.to.shared.u64 t, %1; cvt.u32.u64 %0, t; }"
        : "=r"(sb) : "l"(sm));

    const uint4* gA = g_FA8 + (size_t)(bt * F_SZ + j) * 1024;
    const uint4* gB = g_RB4 + (size_t)p * 1024;
    const uint4* gC = g_FA8 + (size_t)(bt * F_SZ + i) * 1024;

#pragma unroll
    for (int k = 0; k < 8; k++)
        CP_ASYNC16(sb + (uint32_t)(tid + 128 * k) * 16, (const void*)(gA + tid + 128 * k));
    CP_COMMIT();
#pragma unroll
    for (int k = 0; k < 8; k++)
        CP_ASYNC16(sb + 16384u + (uint32_t)(tid + 128 * k) * 16, (const void*)(gB + tid + 128 * k));
    CP_COMMIT();

    const uint4* sA  = reinterpret_cast<const uint4*>(sm);           // [mt8][ksg4][lane32]
    const uint4* sB4 = reinterpret_cast<const uint4*>(sm + 16384);   // [nt16][kp2][lane32]

    CP_WAIT_GROUP(1);
    __syncthreads();

    // A fragments for this warp's 32 rows (mtiles 2w, 2w+1)
    uint32_t Afr[2][4][4];
#pragma unroll
    for (int mt = 0; mt < 2; mt++) {
#pragma unroll
        for (int ksg = 0; ksg < 4; ksg++) {
            uint4 v = sA[((2 * w + mt) * 4 + ksg) * 32 + lane];
            Afr[mt][ksg][0] = v.x; Afr[mt][ksg][1] = v.y;
            Afr[mt][ksg][2] = v.z; Afr[mt][ksg][3] = v.w;
        }
    }

    CP_WAIT_GROUP(0);
    __syncthreads();

    int sel = lane & 1;                // fp8 pair within dword
    int lq  = ((lane & 3) >> 1);       // dword sub-select
    float pacc[2][2] = {{0.f, 0.f}, {0.f, 0.f}};

#pragma unroll
    for (int g4 = 0; g4 < 4; g4++) {                // n (=d) in 4 groups of 32
        // epilogue Fi dwords: fp8 A-frag image (mt''=2w+mt, ksg'=g4), remapped lane
        uint4 ep[2][2];
#pragma unroll
        for (int mt = 0; mt < 2; mt++) {
#pragma unroll
            for (int s = 0; s < 2; s++) {
                int lp = (lane >> 2) * 4 + s * 2 + lq;
                ep[mt][s] = gC[((2 * w + mt) * 4 + g4) * 32 + lp];
            }
        }

        float acc[2][4][4];

#pragma unroll
        for (int kp = 0; kp < 2; kp++) {            // ksg pairs: (0,1), (2,3)
            // one LDS.128 per nt feeds two k-steps (same-lane interleave)
            uint32_t Bfr[4][4];
#pragma unroll
            for (int nt = 0; nt < 4; nt++) {
                uint4 v = sB4[((g4 * 4 + nt) * 2 + kp) * 32 + lane];
                Bfr[nt][0] = v.x; Bfr[nt][1] = v.y;   // ksg = 2kp
                Bfr[nt][2] = v.z; Bfr[nt][3] = v.w;   // ksg = 2kp+1
            }
#pragma unroll
            for (int kh = 0; kh < 2; kh++) {
                int ksg = kp * 2 + kh;
#pragma unroll
                for (int mt = 0; mt < 2; mt++) {
#pragma unroll
                    for (int nt = 0; nt < 4; nt++) {
                        if (ksg == 0)
                            mma16832_zc(acc[mt][nt], Afr[mt][0], &Bfr[nt][0]);
                        else
                            mma16832(acc[mt][nt], Afr[mt][ksg], &Bfr[nt][kh * 2]);
                    }
                }
            }
        }

        // epilogue (v7 mapping): nt0 -> ep[mt][0].x/.y ; nt1 -> ep[mt][1].x/.y
        //                        nt2 -> ep[mt][0].z/.w ; nt3 -> ep[mt][1].z/.w
#pragma unroll
        for (int mt = 0; mt < 2; mt++) {
#pragma unroll
            for (int nt = 0; nt < 4; nt++) {
                const uint4& e = ep[mt][nt & 1];
                uint32_t dw0 = (nt < 2) ? e.x : e.z;
                uint32_t dw1 = (nt < 2) ? e.y : e.w;
                float2 f0 = fp8pair_to_f2(dw0, sel);
                float2 f1 = fp8pair_to_f2(dw1, sel);
                pacc[mt][0] += acc[mt][nt][0] * f0.x + acc[mt][nt][1] * f0.y;
                pacc[mt][1] += acc[mt][nt][2] * f1.x + acc[mt][nt][3] * f1.y;
            }
        }
    }

    // quad reduce (cols live on lanes sharing lane>>2)
#pragma unroll
    for (int mt = 0; mt < 2; mt++)
#pragma unroll
        for (int hh = 0; hh < 2; hh++) {
            pacc[mt][hh] += __shfl_xor_sync(0xffffffffu, pacc[mt][hh], 1);
            pacc[mt][hh] += __shfl_xor_sync(0xffffffffu, pacc[mt][hh], 2);
        }

    if ((lane & 3) == 0) {
#pragma unroll
        for (int mt = 0; mt < 2; mt++) {
#pragma unroll
            for (int hh = 0; hh < 2; hh++) {
                int row = (2 * w + mt) * 16 + (lane >> 2) + hh * 8;
                int bg = bt * 128 + row;
                float res = 0.5f * g_S[bg * F_SZ + i] * g_S[bg * F_SZ + j]
                          + pacc[mt][hh] * R_INVSCALE;
                out[(size_t)bg * (F_SZ * F_SZ) + i * F_SZ + j] = res;
            }
        }
    }
}

// ---------------------------------------------------------------------------
extern "C" void kernel_launch(void* const* d_in, const int* in_sizes, int n_in,
                              void* d_out, int out_size) {
    const float* feature = (const float*)d_in[0];   // [1024, 32, 128] f32
    const float* matrix  = (const float*)d_in[1];   // [32, 32, 128, 128] f32
    float* out = (float*)d_out;                     // [1024, 32, 32] f32

    cudaFuncSetAttribute(main_mma, cudaFuncAttributeMaxDynamicSharedMemorySize, 32768);

    prep_all<<<512 + 2 * NPAIR, 256>>>(feature, matrix, (float4*)out);  // 1504 blocks
    main_mma<<<NPAIR * NBT, 128, 32768>>>(out);                         // 3968 blocks
}